// round 16
// baseline (speedup 1.0000x reference)
#include <cuda_runtime.h>
#include <cstdint>

// Fixed problem shapes
#define NST  32      // categorical variables
#define SS   32      // classes per categorical
#define EE   128     // embedding size

// libdevice accurate logf — the exact function XLA GPU lowers log.f32 to.
extern "C" __device__ float __nv_logf(float);

// Threefry-2x32, 20 rounds, key=(0,42), partitionable layout:
// counter=(hi=0, lo=i); bits = o0^o1.  (Confirmed bit-exact R2..R15.)
__device__ __forceinline__ uint32_t threefry_bits(uint32_t i) {
    const uint32_t k0 = 0u;
    const uint32_t k1 = 42u;
    const uint32_t k2 = 0u ^ 42u ^ 0x1BD11BDAu;
    uint32_t x0 = 0u + k0;
    uint32_t x1 = i + k1;
#define TF_RND(r) { x0 += x1; x1 = __funnelshift_l(x1, x1, (r)) ^ x0; }
    TF_RND(13) TF_RND(15) TF_RND(26) TF_RND(6)   x0 += k1; x1 += k2 + 1u;
    TF_RND(17) TF_RND(29) TF_RND(16) TF_RND(24)  x0 += k2; x1 += k0 + 2u;
    TF_RND(13) TF_RND(15) TF_RND(26) TF_RND(6)   x0 += k0; x1 += k1 + 3u;
    TF_RND(17) TF_RND(29) TF_RND(16) TF_RND(24)  x0 += k1; x1 += k2 + 4u;
    TF_RND(13) TF_RND(15) TF_RND(26) TF_RND(6)   x0 += k2; x1 += k0 + 5u;
#undef TF_RND
    return x0 ^ x1;
}

// bits -> jax uniform(FLT_MIN,1); exact (I2F of <2^23 int, *2^-23, Sterbenz).
__device__ __forceinline__ float uniform_from_bits(uint32_t bits) {
    float f = (float)(bits >> 9) * 1.1920928955078125e-7f;  // 2^-23
    return fmaxf(f, 1.17549435082228750797e-38f);           // FLT_MIN clamp
}

// precise gumbel+logit — bit-exact vs XLA GPU (cold path only)
__device__ __forceinline__ float gumbel_precise(uint32_t bits) {
    return -__nv_logf(-__nv_logf(uniform_from_bits(bits)));
}

// fast gumbel+logit: MUFU.LG2, negations folded into the scale constants,
// final add fused as FFMA. abs error ~1e-5 over the reachable range.
__device__ __forceinline__ float vfast(uint32_t bits, float logit) {
    const float NLN2 = -0.69314718055994530942f;
    float t = __log2f(uniform_from_bits(bits)) * NLN2;   // -ln(u) > 0
    return fmaf(__log2f(t), NLN2, logit);                // -ln(t) + logit
}

// order-preserving float <-> uint transform (monotone)
__device__ __forceinline__ uint32_t float_ordered(float v) {
    uint32_t b = __float_as_uint(v);
    return b ^ (uint32_t)(((int32_t)b >> 31) | (int32_t)0x80000000);
}
// inverse: o top bit 1 (orig positive) -> o^0x80000000; else ~o
__device__ __forceinline__ float ordered_inv(uint32_t o) {
    uint32_t b = o ^ (uint32_t)(((int32_t)(~o) >> 31) | (int32_t)0x80000000);
    return __uint_as_float(b);
}

// fast-path winner must beat all others by E to be provably exact
// (covers fast-log err ~1e-5 + 31-ulp key truncation, both << E)
#define E_MARGIN 1e-3f

#define RPW 4   // rows per warp

__global__ void __launch_bounds__(256)
categorical_encoder_kernel(const float* __restrict__ x,
                           const float* __restrict__ codebook,
                           float* __restrict__ out) {
    const int gwarp = (blockIdx.x * blockDim.x + threadIdx.x) >> 5;  // 0..65535
    const int lane  = threadIdx.x & 31;
    const uint32_t lrev = 31u ^ (uint32_t)lane;   // tiebreak: max key -> lowest lane

    const int rbase = gwarp * RPW;
    const uint32_t ebase = ((uint32_t)rbase << 5) + (uint32_t)lane;

    // prefetch logits — streaming (read exactly once)
    float lgt[RPW];
#pragma unroll
    for (int j = 0; j < RPW; j++)
        lgt[j] = __ldcs(&x[ebase + (uint32_t)j * SS]);

    // 4 independent threefry chains
    uint32_t bits[RPW];
#pragma unroll
    for (int j = 0; j < RPW; j++)
        bits[j] = threefry_bits(ebase + (uint32_t)j * SS);

    // fast-path perturbed logits
    float v[RPW];
#pragma unroll
    for (int j = 0; j < RPW; j++)
        v[j] = vfast(bits[j], lgt[j]);

    // ---- phase 1: packed-key argmax, speculative with exact fallback ----
    // key = (ordered(v) & ~31) | (31^lane): one REDUX gives winner value+lane.
    // Winner value is reconstructed from kmax (NO SHFL): truncation only
    // lowers it, so the margin test stays conservative — borderline rows
    // (including any 32-ulp mispick) fail the test and take the cold path.
    int w[RPW];
    bool safe_all = true;
    bool safe[RPW];
#pragma unroll
    for (int j = 0; j < RPW; j++) {
        const uint32_t key  = (float_ordered(v[j]) & 0xFFFFFFE0u) | lrev;
        const uint32_t kmax = __reduce_max_sync(0xFFFFFFFFu, key);
        w[j] = (int)(31u ^ (kmax & 31u));
        const float t = ordered_inv(kmax & 0xFFFFFFE0u);   // <= true vmax
        safe[j] = (t - v[j] > E_MARGIN) || (lane == w[j]);
        safe_all = safe_all && safe[j];
    }

    int idx[RPW];
    if (__ballot_sync(0xFFFFFFFFu, safe_all) == 0xFFFFFFFFu) {
#pragma unroll
        for (int j = 0; j < RPW; j++) idx[j] = w[j];
    } else {
        // cold path (~0.4% of row-groups): per-row recheck / bit-exact redo
#pragma unroll
        for (int j = 0; j < RPW; j++) {
            if (__ballot_sync(0xFFFFFFFFu, safe[j]) == 0xFFFFFFFFu) {
                idx[j] = w[j];
            } else {
                const float vp = gumbel_precise(bits[j]) + lgt[j];
                const uint32_t up    = float_ordered(vp);
                const uint32_t upmax = __reduce_max_sync(0xFFFFFFFFu, up);
                const uint32_t pbal  = __ballot_sync(0xFFFFFFFFu, up == upmax);
                idx[j] = __ffs(pbal) - 1;   // first-index tiebreak (jnp.argmax)
            }
        }
    }

    // ---- phase 2: all 4 codebook gathers in flight ----
    const int n0 = rbase & (NST - 1);
    const float4* cb = reinterpret_cast<const float4*>(codebook)
                       + ((size_t)n0 * SS) * (EE / 4) + lane;
    float4 tmp[RPW];
#pragma unroll
    for (int j = 0; j < RPW; j++)
        tmp[j] = cb[(size_t)(j * SS + idx[j]) * (EE / 4)];

    // ---- phase 3: all 4 stores — streaming (written once, never re-read) ----
    float4* dst = reinterpret_cast<float4*>(out) + (size_t)rbase * (EE / 4) + lane;
#pragma unroll
    for (int j = 0; j < RPW; j++)
        __stcs(&dst[(size_t)j * (EE / 4)], tmp[j]);
}

extern "C" void kernel_launch(void* const* d_in, const int* in_sizes, int n_in,
                              void* d_out, int out_size) {
    const float* x        = (const float*)d_in[0];
    const float* codebook = (const float*)d_in[1];
    if (n_in >= 2 && in_sizes[0] < in_sizes[1]) {
        x        = (const float*)d_in[1];
        codebook = (const float*)d_in[0];
    }
    float* out = (float*)d_out;

    // 262144 rows, 4 rows/warp, 8 warps/block -> 8192 blocks (65536 warps)
    categorical_encoder_kernel<<<8192, 256>>>(x, codebook, out);
}

// round 17
// speedup vs baseline: 1.0590x; 1.0590x over previous
#include <cuda_runtime.h>
#include <cstdint>

// Fixed problem shapes
#define NST  32      // categorical variables
#define SS   32      // classes per categorical
#define EE   128     // embedding size

// libdevice accurate logf — the exact function XLA GPU lowers log.f32 to.
extern "C" __device__ float __nv_logf(float);

// Threefry-2x32, 20 rounds, key=(0,42), partitionable layout:
// counter=(hi=0, lo=i); bits = o0^o1.  (Confirmed bit-exact R2..R16.)
__device__ __forceinline__ uint32_t threefry_bits(uint32_t i) {
    const uint32_t k0 = 0u;
    const uint32_t k1 = 42u;
    const uint32_t k2 = 0u ^ 42u ^ 0x1BD11BDAu;
    uint32_t x0 = 0u + k0;
    uint32_t x1 = i + k1;
#define TF_RND(r) { x0 += x1; x1 = __funnelshift_l(x1, x1, (r)) ^ x0; }
    TF_RND(13) TF_RND(15) TF_RND(26) TF_RND(6)   x0 += k1; x1 += k2 + 1u;
    TF_RND(17) TF_RND(29) TF_RND(16) TF_RND(24)  x0 += k2; x1 += k0 + 2u;
    TF_RND(13) TF_RND(15) TF_RND(26) TF_RND(6)   x0 += k0; x1 += k1 + 3u;
    TF_RND(17) TF_RND(29) TF_RND(16) TF_RND(24)  x0 += k1; x1 += k2 + 4u;
    TF_RND(13) TF_RND(15) TF_RND(26) TF_RND(6)   x0 += k2; x1 += k0 + 5u;
#undef TF_RND
    return x0 ^ x1;
}

// bits -> jax uniform(FLT_MIN,1); exact (I2F of <2^23 int, *2^-23, Sterbenz).
__device__ __forceinline__ float uniform_from_bits(uint32_t bits) {
    float f = (float)(bits >> 9) * 1.1920928955078125e-7f;  // 2^-23
    return fmaxf(f, 1.17549435082228750797e-38f);           // FLT_MIN clamp
}

// precise gumbel+logit — bit-exact vs XLA GPU (cold path only)
__device__ __forceinline__ float gumbel_precise(uint32_t bits) {
    return -__nv_logf(-__nv_logf(uniform_from_bits(bits)));
}

// fast gumbel+logit: MUFU.LG2, negations folded into the scale constants,
// final add fused as FFMA. abs error ~1e-5 over the reachable range.
__device__ __forceinline__ float vfast(uint32_t bits, float logit) {
    const float NLN2 = -0.69314718055994530942f;
    float t = __log2f(uniform_from_bits(bits)) * NLN2;   // -ln(u) > 0
    return fmaf(__log2f(t), NLN2, logit);                // -ln(t) + logit
}

// order-preserving float -> uint (monotone; equal floats -> equal keys)
__device__ __forceinline__ uint32_t float_ordered(float v) {
    uint32_t b = __float_as_uint(v);
    return b ^ (uint32_t)(((int32_t)b >> 31) | (int32_t)0x80000000);
}

// fast-path winner must beat all others by E to be provably exact
#define E_MARGIN 1e-3f

#define RPW 4   // rows per warp

__global__ void __launch_bounds__(256)
categorical_encoder_kernel(const float* __restrict__ x,
                           const float* __restrict__ codebook,
                           float* __restrict__ out) {
    const int gwarp = (blockIdx.x * blockDim.x + threadIdx.x) >> 5;  // 0..65535
    const int lane  = threadIdx.x & 31;
    const uint32_t lrev = 31u ^ (uint32_t)lane;   // tiebreak: max key -> lowest lane

    const int rbase = gwarp * RPW;
    const uint32_t ebase = ((uint32_t)rbase << 5) + (uint32_t)lane;

    // prefetch logits
    float lgt[RPW];
#pragma unroll
    for (int j = 0; j < RPW; j++)
        lgt[j] = __ldg(&x[ebase + (uint32_t)j * SS]);

    // 4 independent threefry chains
    uint32_t bits[RPW];
#pragma unroll
    for (int j = 0; j < RPW; j++)
        bits[j] = threefry_bits(ebase + (uint32_t)j * SS);

    // fast-path perturbed logits
    float v[RPW];
#pragma unroll
    for (int j = 0; j < RPW; j++)
        v[j] = vfast(bits[j], lgt[j]);

    // ---- phase 1: packed-key argmax, speculative with exact fallback ----
    // key = (ordered(v) & ~31) | (31^lane): one REDUX gives winner value+lane.
    // If the 5 dropped value bits mispick between near-equal lanes, those lanes
    // are within ~32ulp << E_MARGIN, so the margin test fails -> cold path.
    int w[RPW];
    bool safe_all = true;
    bool safe[RPW];
#pragma unroll
    for (int j = 0; j < RPW; j++) {
        const uint32_t key  = (float_ordered(v[j]) & 0xFFFFFFE0u) | lrev;
        const uint32_t kmax = __reduce_max_sync(0xFFFFFFFFu, key);
        w[j] = (int)(31u ^ (kmax & 31u));
        const float vmax = __shfl_sync(0xFFFFFFFFu, v[j], w[j]);
        safe[j] = (vmax - v[j] > E_MARGIN) || (lane == w[j]);
        safe_all = safe_all && safe[j];
    }

    int idx[RPW];
    if (__ballot_sync(0xFFFFFFFFu, safe_all) == 0xFFFFFFFFu) {
#pragma unroll
        for (int j = 0; j < RPW; j++) idx[j] = w[j];
    } else {
        // cold path (~0.4% of row-groups): per-row recheck / bit-exact redo
#pragma unroll
        for (int j = 0; j < RPW; j++) {
            if (__ballot_sync(0xFFFFFFFFu, safe[j]) == 0xFFFFFFFFu) {
                idx[j] = w[j];
            } else {
                const float vp = gumbel_precise(bits[j]) + lgt[j];
                const uint32_t up    = float_ordered(vp);
                const uint32_t upmax = __reduce_max_sync(0xFFFFFFFFu, up);
                const uint32_t pbal  = __ballot_sync(0xFFFFFFFFu, up == upmax);
                idx[j] = __ffs(pbal) - 1;   // first-index tiebreak (jnp.argmax)
            }
        }
    }

    // ---- phase 2: all 4 codebook gathers in flight ----
    const int n0 = rbase & (NST - 1);
    const float4* cb = reinterpret_cast<const float4*>(codebook)
                       + ((size_t)n0 * SS) * (EE / 4) + lane;
    float4 tmp[RPW];
#pragma unroll
    for (int j = 0; j < RPW; j++)
        tmp[j] = cb[(size_t)(j * SS + idx[j]) * (EE / 4)];

    // ---- phase 3: all 4 stores ----
    float4* dst = reinterpret_cast<float4*>(out) + (size_t)rbase * (EE / 4) + lane;
#pragma unroll
    for (int j = 0; j < RPW; j++)
        dst[(size_t)j * (EE / 4)] = tmp[j];
}

extern "C" void kernel_launch(void* const* d_in, const int* in_sizes, int n_in,
                              void* d_out, int out_size) {
    const float* x        = (const float*)d_in[0];
    const float* codebook = (const float*)d_in[1];
    if (n_in >= 2 && in_sizes[0] < in_sizes[1]) {
        x        = (const float*)d_in[1];
        codebook = (const float*)d_in[0];
    }
    float* out = (float*)d_out;

    // 262144 rows, 4 rows/warp, 8 warps/block -> 8192 blocks (65536 warps)
    categorical_encoder_kernel<<<8192, 256>>>(x, codebook, out);
}